// round 1
// baseline (speedup 1.0000x reference)
#include <cuda_runtime.h>
#include <math.h>

// ---------------- static config ----------------
static constexpr int NB = 8;      // batch
static constexpr int ND = 256;    // dim
static constexpr int NC = 64;     // dim/4
static constexpr int NHID = 128;  // mlp hidden
static constexpr int NS = 64;     // state dim
static constexpr int NHH = 28, NWW = 28;
static constexpr int NL = NHH * NWW;  // 784
static constexpr int NHEAD = 16, NHD = 4;

// ---------------- scratch (single __device__ arena) ----------------
// offsets (floats)
static constexpr long O_X1O   = 0;                          // (8,64,784)
static constexpr long O_T1    = O_X1O   + (long)NB*NC*NL;   // (8,128,784)
static constexpr long O_T2    = O_T1    + (long)NB*NHID*NL; // (8,128,784)
static constexpr long O_TMP1  = O_T2    + (long)NB*NHID*NL; // (8,64,784)
static constexpr long O_XT    = O_TMP1  + (long)NB*NC*NL;   // (8,64,100)
static constexpr long O_ATT   = O_XT    + (long)NB*NC*100;  // (8,64,100)
static constexpr long O_BCDT0 = O_ATT   + (long)NB*NC*100;  // (8,192,784)
static constexpr long O_BCDT  = O_BCDT0 + (long)NB*192*NL;  // (8,192,784)
static constexpr long O_H     = O_BCDT  + (long)NB*192*NL;  // (8,64,64)
static constexpr long O_H2    = O_H     + (long)NB*NC*NS;   // (8,64,64)
static constexpr long O_QKV   = O_H2    + (long)NB*NC*NS;   // (8,192,784)
static constexpr long O_O     = O_QKV   + (long)NB*192*NL;  // (8,64,784)
static constexpr long O_XA    = O_O     + (long)NB*NC*NL;   // (8,256,784)
static constexpr long O_M1    = O_XA    + (long)NB*ND*NL;   // (8,128,784)
static constexpr long SCR_TOTAL = O_M1 + (long)NB*NHID*NL;

__device__ float g_scr[SCR_TOTAL];

// ---------------- epilogue modes for pwconv ----------------
enum { M_NONE = 0, M_RELU6, M_MUL, M_ADD_BN, M_BN_RELU, M_BN_ADD, M_BN };

// ---------------- generic 1x1 conv (pointwise GEMM over pixels) ----------------
// out[b][o][l] = epilogue( sum_c w[o][c] * in[b][c][l] )
template <int CIN>
__global__ void pwconv_k(const float* __restrict__ in, long ibs,
                         const float* __restrict__ w, int cout,
                         const float* __restrict__ bias,
                         const float* __restrict__ bnp,
                         const float* __restrict__ res, long rbs,
                         float* __restrict__ out, long obs, int mode) {
    constexpr int OT = 16;
    int b = blockIdx.y;
    int obase = blockIdx.x * OT;
    __shared__ float ws[OT * CIN];
    for (int i = threadIdx.x; i < OT * CIN; i += blockDim.x)
        ws[i] = w[(long)obase * CIN + i];
    __syncthreads();
    const float* ip = in + (long)b * ibs;
    for (int l = threadIdx.x; l < NL; l += blockDim.x) {
        float acc[OT];
#pragma unroll
        for (int i = 0; i < OT; i++) acc[i] = 0.f;
        for (int c = 0; c < CIN; c++) {
            float xv = ip[(long)c * NL + l];
#pragma unroll
            for (int i = 0; i < OT; i++) acc[i] += ws[i * CIN + c] * xv;
        }
#pragma unroll
        for (int i = 0; i < OT; i++) {
            int o = obase + i;
            float s = acc[i];
            if (bias) s += bias[o];
            if (mode == M_RELU6) {
                s = fminf(fmaxf(s, 0.f), 6.f);
            } else if (mode == M_MUL) {
                s *= res[(long)b * rbs + (long)o * NL + l];
            } else if (mode >= M_ADD_BN) {
                if (mode == M_ADD_BN) s += res[(long)b * rbs + (long)o * NL + l];
                float g = bnp[o], be = bnp[cout + o], mm = bnp[2 * cout + o], vv = bnp[3 * cout + o];
                float sc = g * rsqrtf(vv + 1e-5f);
                s = (s - mm) * sc + be;
                if (mode == M_BN_RELU) s = fmaxf(s, 0.f);
                if (mode == M_BN_ADD) s += res[(long)b * rbs + (long)o * NL + l];
            }
            out[(long)b * obs + (long)o * NL + l] = s;
        }
    }
}

// ---------------- depthwise 7x7 (+bias, optional BN) ----------------
__global__ void dw7x7_k(const float* __restrict__ in, long ibs,
                        const float* __restrict__ w, const float* __restrict__ bias,
                        const float* __restrict__ bnp,
                        float* __restrict__ out, long obs) {
    int bc = blockIdx.x;
    int c = bc % NC, b = bc / NC;
    const float* ip = in + (long)b * ibs + (long)c * NL;
    const float* wp = w + c * 49;
    float sc = 1.f, sh = 0.f;
    if (bnp) {
        float g = bnp[c], be = bnp[NC + c], mm = bnp[2 * NC + c], vv = bnp[3 * NC + c];
        sc = g * rsqrtf(vv + 1e-5f);
        sh = be - mm * sc;
    }
    float bi = bias[c];
    for (int l = threadIdx.x; l < NL; l += blockDim.x) {
        int y = l / NWW, x = l % NWW;
        float s = 0.f;
#pragma unroll
        for (int ky = 0; ky < 7; ky++) {
            int yy = y + ky - 3;
            if (yy < 0 || yy >= NHH) continue;
#pragma unroll
            for (int kx = 0; kx < 7; kx++) {
                int xx = x + kx - 3;
                if (xx < 0 || xx >= NWW) continue;
                s += wp[ky * 7 + kx] * ip[yy * NWW + xx];
            }
        }
        s += bi;
        out[(long)b * obs + (long)c * NL + l] = s * sc + sh;
    }
}

// ---------------- depthwise 3x3 (192 ch, no bias) ----------------
__global__ void dw3x3_k(const float* __restrict__ in, const float* __restrict__ w,
                        float* __restrict__ out) {
    int bc = blockIdx.x;
    int c = bc % 192;
    const float* ip = in + (long)bc * NL;
    const float* wp = w + c * 9;
    for (int l = threadIdx.x; l < NL; l += blockDim.x) {
        int y = l / NWW, x = l % NWW;
        float s = 0.f;
#pragma unroll
        for (int ky = 0; ky < 3; ky++) {
            int yy = y + ky - 1;
            if (yy < 0 || yy >= NHH) continue;
#pragma unroll
            for (int kx = 0; kx < 3; kx++) {
                int xx = x + kx - 1;
                if (xx < 0 || xx >= NWW) continue;
                s += wp[ky * 3 + kx] * ip[yy * NWW + xx];
            }
        }
        out[(long)bc * NL + l] = s;
    }
}

// ---------------- maxpool3(s1,p1) + blurpool(f4,s3,reflect(1,2)) fused ----------------
__global__ void pool_blur_k(const float* __restrict__ x, float* __restrict__ xt) {
    int idx = blockIdx.x * blockDim.x + threadIdx.x;
    if (idx >= NB * NC * 100) return;
    int j = idx % 10, i = (idx / 10) % 10, c = (idx / 100) % NC, b = idx / (100 * NC);
    const float* ip = x + ((long)b * ND + NC + c) * NL;  // x2 = channels 64..127
    const float filt[4] = {1.f, 3.f, 3.f, 1.f};
    float s = 0.f;
    for (int fy = 0; fy < 4; fy++) {
        int p = 3 * i + fy;
        int oy = p - 1;
        if (oy < 0) oy = -oy;
        if (oy >= NHH) oy = 2 * NHH - 2 - oy;
        for (int fx = 0; fx < 4; fx++) {
            int q = 3 * j + fx;
            int ox = q - 1;
            if (ox < 0) ox = -ox;
            if (ox >= NWW) ox = 2 * NWW - 2 - ox;
            float mx = -1e30f;
            for (int dy = -1; dy <= 1; dy++) {
                int yy = oy + dy;
                if (yy < 0 || yy >= NHH) continue;
                for (int dx = -1; dx <= 1; dx++) {
                    int xx = ox + dx;
                    if (xx < 0 || xx >= NWW) continue;
                    mx = fmaxf(mx, ip[yy * NWW + xx]);
                }
            }
            s += filt[fy] * filt[fx] * mx;
        }
    }
    xt[idx] = s * (1.f / 64.f);
}

// ---------------- MRA attention map (per (b,c) plane, all in smem) ----------------
__global__ void mra_att_k(const float* __restrict__ xt,
                          const float* __restrict__ h1w, const float* __restrict__ v1w,
                          const float* __restrict__ h2w, const float* __restrict__ v2w,
                          const float* __restrict__ bnp, float* __restrict__ att) {
    int bc = blockIdx.x;
    int c = bc % NC;
    __shared__ float xs[100], ht[190], vt[190], c2[190], c2v[190];
    int t = threadIdx.x;  // 192 threads
    if (t < 100) xs[t] = xt[(long)bc * 100 + t];
    __syncthreads();
    if (t < 190) {
        {   // h-transform: (10,19)
            int k = t, row = k / 20, col = k % 20;
            ht[t] = (col < 10) ? xs[row * 10 + col] : 0.f;
        }
        {   // v-transform: (19,10); vt[a][b2] = h_transform(x^T)[b2][a]
            int a = t / 10, b2 = t % 10;
            int k = b2 * 19 + a, row = k / 20, col = k % 20;
            vt[t] = (col < 10) ? xs[col * 10 + row] : 0.f;
        }
    }
    __syncthreads();
    if (t < 190) {
        {   // conv(11,3) pad(5,1) on ht (10,19)
            int r = t / 19, j = t % 19;
            float s = 0.f;
            for (int ky = 0; ky < 11; ky++) {
                int yy = r + ky - 5;
                if (yy < 0 || yy >= 10) continue;
                for (int kx = 0; kx < 3; kx++) {
                    int xx = j + kx - 1;
                    if (xx < 0 || xx >= 19) continue;
                    s += h2w[c * 33 + ky * 3 + kx] * ht[yy * 19 + xx];
                }
            }
            c2[t] = s;
        }
        {   // conv(3,11) pad(1,5) on vt (19,10)
            int y = t / 10, x2 = t % 10;
            float s = 0.f;
            for (int ky = 0; ky < 3; ky++) {
                int yy = y + ky - 1;
                if (yy < 0 || yy >= 19) continue;
                for (int kx = 0; kx < 11; kx++) {
                    int xx = x2 + kx - 5;
                    if (xx < 0 || xx >= 10) continue;
                    s += v2w[c * 33 + ky * 11 + kx] * vt[yy * 10 + xx];
                }
            }
            c2v[t] = s;
        }
    }
    __syncthreads();
    if (t < 100) {
        int y = t / 10, x = t % 10;
        float s = 0.f;
        // hatt1: (11,3) pad(5,1) on (10,10)
        for (int ky = 0; ky < 11; ky++) {
            int yy = y + ky - 5;
            if (yy < 0 || yy >= 10) continue;
            for (int kx = 0; kx < 3; kx++) {
                int xx = x + kx - 1;
                if (xx < 0 || xx >= 10) continue;
                s += h1w[c * 33 + ky * 3 + kx] * xs[yy * 10 + xx];
            }
        }
        // vatt1: (3,11) pad(1,5)
        for (int ky = 0; ky < 3; ky++) {
            int yy = y + ky - 1;
            if (yy < 0 || yy >= 10) continue;
            for (int kx = 0; kx < 11; kx++) {
                int xx = x + kx - 5;
                if (xx < 0 || xx >= 10) continue;
                s += v1w[c * 33 + ky * 11 + kx] * xs[yy * 10 + xx];
            }
        }
        // inv_h_transform(c2):
        s += c2[y * 20 + x];
        // inv_v_transform(c2v):
        int k4 = x * 20 + y;
        s += c2v[(k4 % 19) * 10 + (k4 / 19)];
        float g = bnp[c], be = bnp[NC + c], mm = bnp[2 * NC + c], vv = bnp[3 * NC + c];
        float sc = g * rsqrtf(vv + 1e-5f);
        s = (s - mm) * sc + be;
        att[(long)bc * 100 + t] = 1.f / (1.f + __expf(-s));
    }
}

// ---------------- apply MRA gate (nearest upsample 10->28) into XA slice 1 ----------------
__global__ void mra_apply_k(const float* __restrict__ x, const float* __restrict__ att,
                            float* __restrict__ xa) {
    int idx = blockIdx.x * blockDim.x + threadIdx.x;
    if (idx >= NB * NC * NL) return;
    int l = idx % NL, c = (idx / NL) % NC, b = idx / (NC * NL);
    int y = l / NWW, xx = l % NWW;
    int yo = (y * 10) / NHH, xo = (xx * 10) / NWW;
    float a = att[((long)b * NC + c) * 100 + yo * 10 + xo];
    long off = (long)b * ND * NL + (long)(NC + c) * NL + l;
    xa[off] = x[off] * a;
}

// ---------------- SSD: softmax over L, fold Bm, h = xs @ (A*Bm)^T ----------------
__global__ void ssd_softmax_h_k(const float* __restrict__ x, const float* __restrict__ bcdt,
                                const float* __restrict__ A_param, float* __restrict__ h) {
    int b = blockIdx.x / 8, sg = blockIdx.x % 8;
    __shared__ float wgt[8][NL];
    __shared__ float red[256];
    int t = threadIdx.x;
    for (int ss = 0; ss < 8; ss++) {
        int s = sg * 8 + ss;
        const float* dt = bcdt + ((long)b * 192 + 128 + s) * NL;
        float ap = A_param[s];
        float mx = -1e30f;
        for (int l = t; l < NL; l += 256) mx = fmaxf(mx, dt[l] + ap);
        red[t] = mx;
        __syncthreads();
        for (int o = 128; o > 0; o >>= 1) {
            if (t < o) red[t] = fmaxf(red[t], red[t + o]);
            __syncthreads();
        }
        mx = red[0];
        __syncthreads();
        float sum = 0.f;
        for (int l = t; l < NL; l += 256) {
            float e = __expf(dt[l] + ap - mx);
            wgt[ss][l] = e;
            sum += e;
        }
        red[t] = sum;
        __syncthreads();
        for (int o = 128; o > 0; o >>= 1) {
            if (t < o) red[t] += red[t + o];
            __syncthreads();
        }
        float inv = 1.f / red[0];
        __syncthreads();
        const float* Bm = bcdt + ((long)b * 192 + s) * NL;
        for (int l = t; l < NL; l += 256) wgt[ss][l] *= inv * Bm[l];
        __syncthreads();
    }
    // h[c][s] = dot(xs[c], wgt[ss]) — warp per output
    int warp = t / 32, lane = t % 32;
    for (int oidx = warp; oidx < NC * 8; oidx += 8) {
        int c = oidx / 8, ss = oidx % 8;
        const float* xs = x + ((long)b * ND + 128 + c) * NL;
        float acc = 0.f;
        for (int l = lane; l < NL; l += 32) acc += xs[l] * wgt[ss][l];
        for (int o = 16; o > 0; o >>= 1) acc += __shfl_down_sync(0xffffffff, acc, o);
        if (lane == 0) h[((long)b * NC + c) * NS + sg * 8 + ss] = acc;
    }
}

// ---------------- SSD: hz / silu gate / out projection (per batch) ----------------
__global__ void ssd_mix_k(const float* __restrict__ h, const float* __restrict__ hzw,
                          const float* __restrict__ ow, const float* __restrict__ D,
                          float* __restrict__ h2) {
    int b = blockIdx.x, t = threadIdx.x;
    __shared__ float hs[NC * NS], u[NC * NS];
    for (int i = t; i < NC * NS; i += 256) hs[i] = h[(long)b * NC * NS + i];
    __syncthreads();
    float Dv = D[0];
    for (int idx = t; idx < NC * NS; idx += 256) {
        int o = idx >> 6, s = idx & 63;
        float s1 = 0.f, s2 = 0.f;
        for (int c = 0; c < NC; c++) {
            float hv = hs[c * NS + s];
            s1 += hzw[o * NC + c] * hv;
            s2 += hzw[(NC + o) * NC + c] * hv;
        }
        float sil = s2 / (1.f + __expf(-s2));
        u[idx] = s1 * sil + s1 * Dv;
    }
    __syncthreads();
    for (int idx = t; idx < NC * NS; idx += 256) {
        int o = idx >> 6, s = idx & 63;
        float acc = 0.f;
        for (int c = 0; c < NC; c++) acc += ow[o * NC + c] * u[c * NS + s];
        h2[(long)b * NC * NS + idx] = acc;
    }
}

// ---------------- SSD: x3 = h2 @ Cm -> XA slice 2 ----------------
__global__ void ssd_out_k(const float* __restrict__ h2, const float* __restrict__ bcdt,
                          float* __restrict__ xa) {
    int b = blockIdx.y, cg = blockIdx.x;  // 4 groups x 16 channels
    __shared__ float hs[16 * NS];
    int t = threadIdx.x;
    for (int i = t; i < 16 * NS; i += 256) hs[i] = h2[((long)b * NC + cg * 16) * NS + i];
    __syncthreads();
    const float* Cm = bcdt + ((long)b * 192 + 64) * NL;
    for (int l = t; l < NL; l += 256) {
        float acc[16];
#pragma unroll
        for (int i = 0; i < 16; i++) acc[i] = 0.f;
        for (int s = 0; s < NS; s++) {
            float cv = Cm[(long)s * NL + l];
#pragma unroll
            for (int i = 0; i < 16; i++) acc[i] += hs[i * NS + s] * cv;
        }
#pragma unroll
        for (int i = 0; i < 16; i++)
            xa[(long)b * ND * NL + (long)(128 + cg * 16 + i) * NL + l] = acc[i];
    }
}

// ---------------- GA attention: one thread per query row, K/V in smem ----------------
__global__ void attn_k(const float* __restrict__ qkv, float* __restrict__ o) {
    int blk = blockIdx.x;
    int rc = blk % 7;
    int bh = blk / 7;
    int head = bh % NHEAD, b = bh / NHEAD;
    __shared__ float Ks[NL * 4], Vs[NL * 4];
    const float* kbase = qkv + ((long)b * 192 + 64 + head * 4) * NL;
    const float* vbase = qkv + ((long)b * 192 + 128 + head * 4) * NL;
    for (int i = threadIdx.x; i < NL * 4; i += blockDim.x) {
        int d = i / NL, l = i % NL;
        Ks[l * 4 + d] = kbase[i];
        Vs[l * 4 + d] = vbase[i];
    }
    __syncthreads();
    int row = rc * 128 + threadIdx.x;
    if (row >= NL) return;
    const float* qb = qkv + ((long)b * 192 + head * 4) * NL;
    float q0 = qb[row], q1 = qb[NL + row], q2 = qb[2 * NL + row], q3 = qb[3 * NL + row];
    float m = -1e30f, se = 0.f, a0 = 0.f, a1 = 0.f, a2 = 0.f, a3 = 0.f;
    const float4* K4 = reinterpret_cast<const float4*>(Ks);
    const float4* V4 = reinterpret_cast<const float4*>(Vs);
    for (int l = 0; l < NL; l++) {
        float4 kv = K4[l];
        float s = (q0 * kv.x + q1 * kv.y + q2 * kv.z + q3 * kv.w) * 0.5f;
        if (s > m) {
            float r = __expf(m - s);
            se *= r; a0 *= r; a1 *= r; a2 *= r; a3 *= r;
            m = s;
        }
        float p = __expf(s - m);
        float4 vv = V4[l];
        se += p;
        a0 += p * vv.x; a1 += p * vv.y; a2 += p * vv.z; a3 += p * vv.w;
    }
    float inv = 1.f / se;
    float* ob = o + ((long)b * NC + head * 4) * NL;
    ob[row] = a0 * inv;
    ob[NL + row] = a1 * inv;
    ob[2 * NL + row] = a2 * inv;
    ob[3 * NL + row] = a3 * inv;
}

// ---------------- launch ----------------
extern "C" void kernel_launch(void* const* d_in, const int* in_sizes, int n_in,
                              void* d_out, int out_size) {
    const float* x       = (const float*)d_in[0];
    const float* dw1_w   = (const float*)d_in[1];
    const float* dw1_b   = (const float*)d_in[2];
    const float* bn_dw1  = (const float*)d_in[3];
    const float* f1_w    = (const float*)d_in[4];
    const float* f1_b    = (const float*)d_in[5];
    const float* f2_w    = (const float*)d_in[6];
    const float* f2_b    = (const float*)d_in[7];
    const float* g_w     = (const float*)d_in[8];
    const float* g_b     = (const float*)d_in[9];
    const float* bn_g    = (const float*)d_in[10];
    const float* dw2_w   = (const float*)d_in[11];
    const float* dw2_b   = (const float*)d_in[12];
    const float* hatt1_w = (const float*)d_in[13];
    const float* vatt1_w = (const float*)d_in[14];
    const float* hatt2_w = (const float*)d_in[15];
    const float* vatt2_w = (const float*)d_in[16];
    const float* bn_mra  = (const float*)d_in[17];
    const float* bcdt_w  = (const float*)d_in[18];
    const float* ssd_dw  = (const float*)d_in[19];
    const float* hz_w    = (const float*)d_in[20];
    const float* out_w   = (const float*)d_in[21];
    const float* A_param = (const float*)d_in[22];
    const float* D_param = (const float*)d_in[23];
    const float* qkv_w   = (const float*)d_in[24];
    const float* proj_w  = (const float*)d_in[25];
    const float* bn_n4   = (const float*)d_in[26];
    const float* mlp1_w  = (const float*)d_in[27];
    const float* bn_mlp  = (const float*)d_in[28];
    const float* mlp2_w  = (const float*)d_in[29];
    const float* bn_n1   = (const float*)d_in[30];
    float* out = (float*)d_out;

    float* scr = nullptr;
    cudaGetSymbolAddress((void**)&scr, g_scr);
    float* x1o   = scr + O_X1O;
    float* t1    = scr + O_T1;
    float* t2    = scr + O_T2;
    float* tmp1  = scr + O_TMP1;
    float* xt    = scr + O_XT;
    float* att   = scr + O_ATT;
    float* bcdt0 = scr + O_BCDT0;
    float* bcdt  = scr + O_BCDT;
    float* hbuf  = scr + O_H;
    float* h2    = scr + O_H2;
    float* qkv   = scr + O_QKV;
    float* obuf  = scr + O_O;
    float* xa    = scr + O_XA;
    float* m1    = scr + O_M1;

    const long XBS = (long)ND * NL;   // batch stride of x / xa / out
    const long C64 = (long)NC * NL;
    const long C128 = (long)NHID * NL;
    const long C192 = (long)192 * NL;

    // ---- branch 1 ----
    dw7x7_k<<<NB * NC, 256>>>(x, XBS, dw1_w, dw1_b, bn_dw1, x1o, C64);
    pwconv_k<64><<<dim3(NHID / 16, NB), 256>>>(x1o, C64, f1_w, NHID, f1_b, nullptr,
                                               nullptr, 0, t1, C128, M_RELU6);
    pwconv_k<64><<<dim3(NHID / 16, NB), 256>>>(x1o, C64, f2_w, NHID, f2_b, nullptr,
                                               t1, C128, t2, C128, M_MUL);
    pwconv_k<128><<<dim3(NC / 16, NB), 256>>>(t2, C128, g_w, NC, g_b, bn_g,
                                              nullptr, 0, tmp1, C64, M_BN);
    dw7x7_k<<<NB * NC, 256>>>(tmp1, C64, dw2_w, dw2_b, nullptr, xa, XBS);  // slice 0

    // ---- branch 2 ----
    pool_blur_k<<<(NB * NC * 100 + 255) / 256, 256>>>(x, xt);
    mra_att_k<<<NB * NC, 192>>>(xt, hatt1_w, vatt1_w, hatt2_w, vatt2_w, bn_mra, att);
    mra_apply_k<<<(NB * NC * NL + 255) / 256, 256>>>(x, att, xa);  // slice 1

    // ---- branch 3 ----
    pwconv_k<64><<<dim3(192 / 16, NB), 256>>>(x + 128 * NL, XBS, bcdt_w, 192, nullptr,
                                              nullptr, nullptr, 0, bcdt0, C192, M_NONE);
    dw3x3_k<<<NB * 192, 256>>>(bcdt0, ssd_dw, bcdt);
    ssd_softmax_h_k<<<NB * 8, 256>>>(x, bcdt, A_param, hbuf);
    ssd_mix_k<<<NB, 256>>>(hbuf, hz_w, out_w, D_param, h2);
    ssd_out_k<<<dim3(4, NB), 256>>>(h2, bcdt, xa);  // slice 2

    // ---- branch 4 ----
    pwconv_k<64><<<dim3(192 / 16, NB), 256>>>(x + 192 * NL, XBS, qkv_w, 192, nullptr,
                                              nullptr, nullptr, 0, qkv, C192, M_NONE);
    attn_k<<<NB * NHEAD * 7, 128>>>(qkv, obuf);
    pwconv_k<64><<<dim3(NC / 16, NB), 256>>>(obuf, C64, proj_w, NC, nullptr, bn_n4,
                                             x + 192 * NL, XBS, xa + 192 * NL, XBS,
                                             M_ADD_BN);  // slice 3

    // ---- merge MLP + residual ----
    pwconv_k<256><<<dim3(NHID / 16, NB), 256>>>(xa, XBS, mlp1_w, NHID, nullptr, bn_mlp,
                                                nullptr, 0, m1, C128, M_BN_RELU);
    pwconv_k<128><<<dim3(ND / 16, NB), 256>>>(m1, C128, mlp2_w, ND, nullptr, bn_n1,
                                              x, XBS, out, XBS, M_BN_ADD);
}

// round 3
// speedup vs baseline: 2.7903x; 2.7903x over previous
#include <cuda_runtime.h>
#include <math.h>

// ---------------- static config ----------------
static constexpr int NB = 8;
static constexpr int ND = 256;
static constexpr int NC = 64;
static constexpr int NHID = 128;
static constexpr int NS = 64;
static constexpr int NHH = 28, NWW = 28;
static constexpr int NL = NHH * NWW;      // 784
static constexpr int NHEAD = 16;
static constexpr int NPAIRS = NB * NL / 2;  // 3136
static constexpr int PPB = NL / 2;          // 392 pairs per batch

// ---------------- scratch arena ----------------
static constexpr long O_X1O   = 0;                          // (8,64,784)
static constexpr long O_W     = O_X1O   + (long)NB*NC*NL;   // ssd softmax weights (8,64,784)
static constexpr long O_T2    = O_W     + (long)NB*NS*NL;   // star out (8,128,784); later u (8,64,64)
static constexpr long O_TMP1  = O_T2    + (long)NB*NHID*NL; // (8,64,784)
static constexpr long O_XT    = O_TMP1  + (long)NB*NC*NL;   // (8,64,100)
static constexpr long O_ATT   = O_XT    + (long)NB*NC*100;  // (8,64,100)
static constexpr long O_BCDT0 = O_ATT   + (long)NB*NC*100;  // (8,192,784)
static constexpr long O_BCDT  = O_BCDT0 + (long)NB*192*NL;  // (8,192,784)
static constexpr long O_H     = O_BCDT  + (long)NB*192*NL;  // (8,64,64)
static constexpr long O_H2    = O_H     + (long)NB*NC*NS;   // (8,64,64)
static constexpr long O_U     = O_H2    + (long)NB*NC*NS;   // (8,64,64)
static constexpr long O_QKV   = O_U     + (long)NB*NC*NS;   // (8,192,784)
static constexpr long O_O     = O_QKV   + (long)NB*192*NL;  // (8,64,784)
static constexpr long O_XA    = O_O     + (long)NB*NC*NL;   // (8,256,784)
static constexpr long O_M1    = O_XA    + (long)NB*ND*NL;   // (8,128,784)
static constexpr long SCR_TOTAL = O_M1 + (long)NB*NHID*NL;

__device__ __align__(16) float g_scr[SCR_TOTAL];

enum { M_NONE = 0, M_ADD_BN, M_BN_RELU, M_BN_ADD, M_BN };

// ---------------- pointwise conv, pixel-pair tiled ----------------
// grid: (cout/16, 25).  block: 128 threads, each = 1 float2 pixel pair.
template <int CIN>
__global__ void pwconv_k(const float* __restrict__ in, long ibs,
                         const float* __restrict__ w, int cout,
                         const float* __restrict__ bias,
                         const float* __restrict__ bnp,
                         const float* __restrict__ res, long rbs,
                         float* __restrict__ out, long obs, int mode) {
    constexpr int OT = 16;
    __shared__ float ws[CIN * OT];  // transposed: ws[c*16+i]
    int obase = blockIdx.x * OT;
    for (int idx = threadIdx.x; idx < CIN * OT; idx += 128) {
        int c = idx >> 4, i = idx & 15;
        ws[idx] = w[(long)(obase + i) * CIN + c];
    }
    __syncthreads();
    int pp = blockIdx.y * 128 + threadIdx.x;
    if (pp >= NPAIRS) return;
    int b = pp / PPB;
    int l = (pp % PPB) * 2;
    const float2* ip2 = reinterpret_cast<const float2*>(in + (long)b * ibs + l);

    float a0[OT], a1[OT];
#pragma unroll
    for (int i = 0; i < OT; i++) { a0[i] = 0.f; a1[i] = 0.f; }
#pragma unroll 4
    for (int c = 0; c < CIN; c++) {
        float2 xv = ip2[c * (NL / 2)];
        const float* wc = ws + c * OT;
#pragma unroll
        for (int i = 0; i < OT; i++) {
            float wv = wc[i];
            a0[i] += wv * xv.x;
            a1[i] += wv * xv.y;
        }
    }
#pragma unroll
    for (int i = 0; i < OT; i++) {
        int o = obase + i;
        float s0 = a0[i], s1 = a1[i];
        if (bias) { s0 += bias[o]; s1 += bias[o]; }
        if (mode >= M_ADD_BN) {
            long roff = (long)b * rbs + (long)o * NL + l;
            if (mode == M_ADD_BN) {
                float2 rv = *reinterpret_cast<const float2*>(res + roff);
                s0 += rv.x; s1 += rv.y;
            }
            float g = bnp[o], be = bnp[cout + o], mm = bnp[2 * cout + o], vv = bnp[3 * cout + o];
            float sc = g * rsqrtf(vv + 1e-5f);
            s0 = (s0 - mm) * sc + be;
            s1 = (s1 - mm) * sc + be;
            if (mode == M_BN_RELU) { s0 = fmaxf(s0, 0.f); s1 = fmaxf(s1, 0.f); }
            if (mode == M_BN_ADD) {
                float2 rv = *reinterpret_cast<const float2*>(res + roff);
                s0 += rv.x; s1 += rv.y;
            }
        }
        *reinterpret_cast<float2*>(out + (long)b * obs + (long)o * NL + l) =
            make_float2(s0, s1);
    }
}

// ---------------- fused star: t2 = relu6(f1(x)) * f2(x), CIN=64, 16 hid/block ----------------
__global__ void star_k(const float* __restrict__ in,
                       const float* __restrict__ w1, const float* __restrict__ b1,
                       const float* __restrict__ w2, const float* __restrict__ b2,
                       float* __restrict__ out) {
    constexpr int OT = 16, CIN = NC;
    __shared__ float ws1[CIN * OT], ws2[CIN * OT];
    int obase = blockIdx.x * OT;
    for (int idx = threadIdx.x; idx < CIN * OT; idx += 128) {
        int c = idx >> 4, i = idx & 15;
        ws1[idx] = w1[(long)(obase + i) * CIN + c];
        ws2[idx] = w2[(long)(obase + i) * CIN + c];
    }
    __syncthreads();
    int pp = blockIdx.y * 128 + threadIdx.x;
    if (pp >= NPAIRS) return;
    int b = pp / PPB;
    int l = (pp % PPB) * 2;
    const float2* ip2 = reinterpret_cast<const float2*>(in + (long)b * NC * NL + l);

    float p0[OT], p1[OT], q0[OT], q1[OT];
#pragma unroll
    for (int i = 0; i < OT; i++) { p0[i] = p1[i] = q0[i] = q1[i] = 0.f; }
#pragma unroll 4
    for (int c = 0; c < CIN; c++) {
        float2 xv = ip2[c * (NL / 2)];
        const float* w1c = ws1 + c * OT;
        const float* w2c = ws2 + c * OT;
#pragma unroll
        for (int i = 0; i < OT; i++) {
            p0[i] += w1c[i] * xv.x; p1[i] += w1c[i] * xv.y;
            q0[i] += w2c[i] * xv.x; q1[i] += w2c[i] * xv.y;
        }
    }
#pragma unroll
    for (int i = 0; i < OT; i++) {
        int o = obase + i;
        float h0 = fminf(fmaxf(p0[i] + b1[o], 0.f), 6.f);
        float h1 = fminf(fmaxf(p1[i] + b1[o], 0.f), 6.f);
        float s0 = h0 * (q0[i] + b2[o]);
        float s1 = h1 * (q1[i] + b2[o]);
        *reinterpret_cast<float2*>(out + ((long)b * NHID + o) * NL + l) =
            make_float2(s0, s1);
    }
}

// ---------------- depthwise 7x7, smem plane ----------------
__global__ void dw7x7_k(const float* __restrict__ in, long ibs,
                        const float* __restrict__ w, const float* __restrict__ bias,
                        const float* __restrict__ bnp,
                        float* __restrict__ out, long obs) {
    int bc = blockIdx.x;
    int c = bc % NC, b = bc / NC;
    const float* ip = in + (long)b * ibs + (long)c * NL;
    __shared__ float pl[34 * 34];
    __shared__ float wsh[49];
    int t = threadIdx.x;
    for (int i = t; i < 34 * 34; i += 256) pl[i] = 0.f;
    if (t < 49) wsh[t] = w[c * 49 + t];
    __syncthreads();
    for (int i = t; i < NL; i += 256) {
        int y = i / NWW, x = i % NWW;
        pl[(y + 3) * 34 + x + 3] = ip[i];
    }
    __syncthreads();
    float sc = 1.f, sh = 0.f;
    if (bnp) {
        float g = bnp[c], be = bnp[NC + c], mm = bnp[2 * NC + c], vv = bnp[3 * NC + c];
        sc = g * rsqrtf(vv + 1e-5f);
        sh = be - mm * sc;
    }
    float bi = bias[c];
    for (int i = t; i < NL; i += 256) {
        int y = i / NWW, x = i % NWW;
        float s = 0.f;
#pragma unroll
        for (int ky = 0; ky < 7; ky++)
#pragma unroll
            for (int kx = 0; kx < 7; kx++)
                s += wsh[ky * 7 + kx] * pl[(y + ky) * 34 + x + kx];
        s += bi;
        out[(long)b * obs + (long)c * NL + i] = s * sc + sh;
    }
}

// ---------------- depthwise 3x3 (192 ch), smem plane ----------------
__global__ void dw3x3_k(const float* __restrict__ in, const float* __restrict__ w,
                        float* __restrict__ out) {
    int bc = blockIdx.x;
    int c = bc % 192;
    const float* ip = in + (long)bc * NL;
    __shared__ float pl[30 * 30];
    __shared__ float wsh[9];
    int t = threadIdx.x;
    for (int i = t; i < 30 * 30; i += 256) pl[i] = 0.f;
    if (t < 9) wsh[t] = w[c * 9 + t];
    __syncthreads();
    for (int i = t; i < NL; i += 256) {
        int y = i / NWW, x = i % NWW;
        pl[(y + 1) * 30 + x + 1] = ip[i];
    }
    __syncthreads();
    for (int i = t; i < NL; i += 256) {
        int y = i / NWW, x = i % NWW;
        float s = 0.f;
#pragma unroll
        for (int ky = 0; ky < 3; ky++)
#pragma unroll
            for (int kx = 0; kx < 3; kx++)
                s += wsh[ky * 3 + kx] * pl[(y + ky) * 30 + x + kx];
        out[(long)bc * NL + i] = s;
    }
}

// ---------------- maxpool3 + blurpool fused ----------------
__global__ void pool_blur_k(const float* __restrict__ x, float* __restrict__ xt) {
    int idx = blockIdx.x * blockDim.x + threadIdx.x;
    if (idx >= NB * NC * 100) return;
    int j = idx % 10, i = (idx / 10) % 10, c = (idx / 100) % NC, b = idx / (100 * NC);
    const float* ip = x + ((long)b * ND + NC + c) * NL;
    const float filt[4] = {1.f, 3.f, 3.f, 1.f};
    float s = 0.f;
    for (int fy = 0; fy < 4; fy++) {
        int oy = 3 * i + fy - 1;
        if (oy < 0) oy = -oy;
        if (oy >= NHH) oy = 2 * NHH - 2 - oy;
        for (int fx = 0; fx < 4; fx++) {
            int ox = 3 * j + fx - 1;
            if (ox < 0) ox = -ox;
            if (ox >= NWW) ox = 2 * NWW - 2 - ox;
            float mx = -1e30f;
            for (int dy = -1; dy <= 1; dy++) {
                int yy = oy + dy;
                if (yy < 0 || yy >= NHH) continue;
                for (int dx = -1; dx <= 1; dx++) {
                    int xx = ox + dx;
                    if (xx < 0 || xx >= NWW) continue;
                    mx = fmaxf(mx, ip[yy * NWW + xx]);
                }
            }
            s += filt[fy] * filt[fx] * mx;
        }
    }
    xt[idx] = s * (1.f / 64.f);
}

// ---------------- MRA attention map ----------------
__global__ void mra_att_k(const float* __restrict__ xt,
                          const float* __restrict__ h1w, const float* __restrict__ v1w,
                          const float* __restrict__ h2w, const float* __restrict__ v2w,
                          const float* __restrict__ bnp, float* __restrict__ att) {
    int bc = blockIdx.x;
    int c = bc % NC;
    __shared__ float xs[100], ht[190], vt[190], c2[190], c2v[190];
    int t = threadIdx.x;  // 192 threads
    if (t < 100) xs[t] = xt[(long)bc * 100 + t];
    __syncthreads();
    if (t < 190) {
        {
            int row = t / 20, col = t % 20;
            ht[t] = (col < 10) ? xs[row * 10 + col] : 0.f;
        }
        {
            int a = t / 10, b2 = t % 10;
            int k = b2 * 19 + a, row = k / 20, col = k % 20;
            vt[t] = (col < 10) ? xs[col * 10 + row] : 0.f;
        }
    }
    __syncthreads();
    if (t < 190) {
        {
            int r = t / 19, j = t % 19;
            float s = 0.f;
            for (int ky = 0; ky < 11; ky++) {
                int yy = r + ky - 5;
                if (yy < 0 || yy >= 10) continue;
                for (int kx = 0; kx < 3; kx++) {
                    int xx = j + kx - 1;
                    if (xx < 0 || xx >= 19) continue;
                    s += h2w[c * 33 + ky * 3 + kx] * ht[yy * 19 + xx];
                }
            }
            c2[t] = s;
        }
        {
            int y = t / 10, x2 = t % 10;
            float s = 0.f;
            for (int ky = 0; ky < 3; ky++) {
                int yy = y + ky - 1;
                if (yy < 0 || yy >= 19) continue;
                for (int kx = 0; kx < 11; kx++) {
                    int xx = x2 + kx - 5;
                    if (xx < 0 || xx >= 10) continue;
                    s += v2w[c * 33 + ky * 11 + kx] * vt[yy * 10 + xx];
                }
            }
            c2v[t] = s;
        }
    }
    __syncthreads();
    if (t < 100) {
        int y = t / 10, x = t % 10;
        float s = 0.f;
        for (int ky = 0; ky < 11; ky++) {
            int yy = y + ky - 5;
            if (yy < 0 || yy >= 10) continue;
            for (int kx = 0; kx < 3; kx++) {
                int xx = x + kx - 1;
                if (xx < 0 || xx >= 10) continue;
                s += h1w[c * 33 + ky * 3 + kx] * xs[yy * 10 + xx];
            }
        }
        for (int ky = 0; ky < 3; ky++) {
            int yy = y + ky - 1;
            if (yy < 0 || yy >= 10) continue;
            for (int kx = 0; kx < 11; kx++) {
                int xx = x + kx - 5;
                if (xx < 0 || xx >= 10) continue;
                s += v1w[c * 33 + ky * 11 + kx] * xs[yy * 10 + xx];
            }
        }
        s += c2[y * 20 + x];
        int k4 = x * 20 + y;
        s += c2v[(k4 % 19) * 10 + (k4 / 19)];
        float g = bnp[c], be = bnp[NC + c], mm = bnp[2 * NC + c], vv = bnp[3 * NC + c];
        float sc = g * rsqrtf(vv + 1e-5f);
        s = (s - mm) * sc + be;
        att[(long)bc * 100 + t] = 1.f / (1.f + __expf(-s));
    }
}

// ---------------- apply MRA gate ----------------
__global__ void mra_apply_k(const float* __restrict__ x, const float* __restrict__ att,
                            float* __restrict__ xa) {
    int idx = blockIdx.x * blockDim.x + threadIdx.x;
    if (idx >= NB * NC * NL) return;
    int l = idx % NL, c = (idx / NL) % NC, b = idx / (NC * NL);
    int y = l / NWW, xx = l % NWW;
    int yo = (y * 10) / NHH, xo = (xx * 10) / NWW;
    float a = att[((long)b * NC + c) * 100 + yo * 10 + xo];
    long off = (long)b * ND * NL + (long)(NC + c) * NL + l;
    xa[off] = x[off] * a;
}

// ---------------- SSD softmax weights: W[b][s][l] = softmax(dt+A)[l]*Bm[l] ----------------
__global__ void ssd_W_k(const float* __restrict__ bcdt, const float* __restrict__ A_param,
                        float* __restrict__ W) {
    int b = blockIdx.x / NS, s = blockIdx.x % NS;
    const float* dt = bcdt + ((long)b * 192 + 128 + s) * NL;
    const float* Bm = bcdt + ((long)b * 192 + s) * NL;
    float* Wp = W + ((long)b * NS + s) * NL;
    __shared__ float red[256];
    int t = threadIdx.x;
    float ap = A_param[s];
    float mx = -1e30f;
    for (int l = t; l < NL; l += 256) mx = fmaxf(mx, dt[l] + ap);
    red[t] = mx;
    __syncthreads();
    for (int o = 128; o > 0; o >>= 1) {
        if (t < o) red[t] = fmaxf(red[t], red[t + o]);
        __syncthreads();
    }
    mx = red[0];
    __syncthreads();
    float sum = 0.f;
    for (int l = t; l < NL; l += 256) {
        float e = __expf(dt[l] + ap - mx);
        Wp[l] = e;
        sum += e;
    }
    red[t] = sum;
    __syncthreads();
    for (int o = 128; o > 0; o >>= 1) {
        if (t < o) red[t] += red[t + o];
        __syncthreads();
    }
    float inv = 1.f / red[0];
    __syncthreads();
    for (int l = t; l < NL; l += 256) Wp[l] = Wp[l] * inv * Bm[l];
}

// ---------------- SSD h = xs @ W^T : grid (8 ctile, 8 stile, NB) ----------------
__global__ void ssd_h_k(const float* __restrict__ x, const float* __restrict__ W,
                        float* __restrict__ h) {
    int b = blockIdx.z;
    int sbase = blockIdx.y * 8;
    __shared__ float Wt[8][NL];
    int t = threadIdx.x;
    for (int i = t; i < 8 * NL; i += 256) {
        int si = i / NL, l = i % NL;
        Wt[si][l] = W[((long)b * NS + sbase + si) * NL + l];
    }
    __syncthreads();
    int warp = t / 32, lane = t % 32;
    int c = blockIdx.x * 8 + warp;
    const float* xs = x + ((long)b * ND + 128 + c) * NL;
    float acc[8];
#pragma unroll
    for (int i = 0; i < 8; i++) acc[i] = 0.f;
    for (int l = lane; l < NL; l += 32) {
        float xv = xs[l];
#pragma unroll
        for (int i = 0; i < 8; i++) acc[i] += xv * Wt[i][l];
    }
#pragma unroll
    for (int i = 0; i < 8; i++) {
        for (int o = 16; o > 0; o >>= 1) acc[i] += __shfl_down_sync(0xffffffff, acc[i], o);
    }
    if (lane == 0) {
#pragma unroll
        for (int i = 0; i < 8; i++)
            h[((long)b * NC + c) * NS + sbase + i] = acc[i];
    }
}

// ---------------- SSD mix stage 1: u = hz1(h) * (silu(hz2(h)) + D) ----------------
__global__ void ssd_mix1_k(const float* __restrict__ h, const float* __restrict__ hzw,
                           const float* __restrict__ D, float* __restrict__ u) {
    int b = blockIdx.y, og = blockIdx.x, t = threadIdx.x;
    __shared__ float hs[NC * NS];
    __shared__ float w1[16 * NC], w2[16 * NC];
    for (int i = t; i < NC * NS; i += 256) hs[i] = h[(long)b * NC * NS + i];
    for (int i = t; i < 16 * NC; i += 256) {
        int o = i / NC, c = i % NC;
        w1[i] = hzw[(og * 16 + o) * NC + c];
        w2[i] = hzw[(NC + og * 16 + o) * NC + c];
    }
    __syncthreads();
    float Dv = D[0];
    for (int idx = t; idx < 16 * NS; idx += 256) {
        int o = idx / NS, s = idx % NS;
        float s1 = 0.f, s2 = 0.f;
#pragma unroll 4
        for (int c = 0; c < NC; c++) {
            float hv = hs[c * NS + s];
            s1 += w1[o * NC + c] * hv;
            s2 += w2[o * NC + c] * hv;
        }
        float sil = s2 / (1.f + __expf(-s2));
        u[((long)b * NC + og * 16 + o) * NS + s] = s1 * sil + s1 * Dv;
    }
}

// ---------------- SSD mix stage 2: h2 = out_w @ u ----------------
__global__ void ssd_mix2_k(const float* __restrict__ u, const float* __restrict__ ow,
                           float* __restrict__ h2) {
    int b = blockIdx.y, og = blockIdx.x, t = threadIdx.x;
    __shared__ float us[NC * NS];
    __shared__ float wsm[16 * NC];
    for (int i = t; i < NC * NS; i += 256) us[i] = u[(long)b * NC * NS + i];
    for (int i = t; i < 16 * NC; i += 256)
        wsm[i] = ow[(og * 16 + i / NC) * NC + i % NC];
    __syncthreads();
    for (int idx = t; idx < 16 * NS; idx += 256) {
        int o = idx / NS, s = idx % NS;
        float acc = 0.f;
#pragma unroll 4
        for (int c = 0; c < NC; c++) acc += wsm[o * NC + c] * us[c * NS + s];
        h2[((long)b * NC + og * 16 + o) * NS + s] = acc;
    }
}

// ---------------- SSD out: x3 = h2 @ Cm, grid (4 cg, 4 lt, NB) ----------------
__global__ void ssd_out_k(const float* __restrict__ h2, const float* __restrict__ bcdt,
                          float* __restrict__ xa) {
    int b = blockIdx.z, lt = blockIdx.y, cg = blockIdx.x;
    __shared__ float hst[NS * 16];  // transposed: hst[s*16+i]
    int t = threadIdx.x;  // 196
    for (int i = t; i < 16 * NS; i += 196) {
        int s = i / 16, ii = i % 16;
        hst[i] = h2[((long)b * NC + cg * 16 + ii) * NS + s];
    }
    __syncthreads();
    int l = lt * 196 + t;
    const float* Cm = bcdt + ((long)b * 192 + 64) * NL + l;
    float acc[16];
#pragma unroll
    for (int i = 0; i < 16; i++) acc[i] = 0.f;
#pragma unroll 4
    for (int s = 0; s < NS; s++) {
        float cv = Cm[(long)s * NL];
        const float* hp = hst + s * 16;
#pragma unroll
        for (int i = 0; i < 16; i++) acc[i] += hp[i] * cv;
    }
#pragma unroll
    for (int i = 0; i < 16; i++)
        xa[(long)b * ND * NL + (long)(128 + cg * 16 + i) * NL + l] = acc[i];
}

// ---------------- GA attention: single-pass softmax (scores bounded) ----------------
__global__ void attn_k(const float* __restrict__ qkv, float* __restrict__ o) {
    int blk = blockIdx.x;
    int rc = blk % 7;
    int bh = blk / 7;
    int head = bh % NHEAD, b = bh / NHEAD;
    __shared__ float Ks[NL * 4], Vs[NL * 4];
    const float* kbase = qkv + ((long)b * 192 + 64 + head * 4) * NL;
    const float* vbase = qkv + ((long)b * 192 + 128 + head * 4) * NL;
    for (int i = threadIdx.x; i < NL * 4; i += blockDim.x) {
        int d = i / NL, l = i % NL;
        Ks[l * 4 + d] = kbase[i];
        Vs[l * 4 + d] = vbase[i];
    }
    __syncthreads();
    int row = rc * 128 + threadIdx.x;
    if (row >= NL) return;
    const float* qb = qkv + ((long)b * 192 + head * 4) * NL;
    float q0 = qb[row] * 0.5f, q1 = qb[NL + row] * 0.5f;
    float q2 = qb[2 * NL + row] * 0.5f, q3 = qb[3 * NL + row] * 0.5f;
    float se = 0.f, a0 = 0.f, a1 = 0.f, a2 = 0.f, a3 = 0.f;
    const float4* K4 = reinterpret_cast<const float4*>(Ks);
    const float4* V4 = reinterpret_cast<const float4*>(Vs);
    for (int l = 0; l < NL; l++) {
        float4 kv = K4[l];
        float s = q0 * kv.x + q1 * kv.y + q2 * kv.z + q3 * kv.w;
        float p = __expf(s);
        float4 vv = V4[l];
        se += p;
        a0 += p * vv.x; a1 += p * vv.y; a2 += p * vv.z; a3 += p * vv.w;
    }
    float inv = 1.f / se;
    float* ob = o + ((long)b * NC + head * 4) * NL;
    ob[row] = a0 * inv;
    ob[NL + row] = a1 * inv;
    ob[2 * NL + row] = a2 * inv;
    ob[3 * NL + row] = a3 * inv;
}

// ---------------- launch ----------------
extern "C" void kernel_launch(void* const* d_in, const int* in_sizes, int n_in,
                              void* d_out, int out_size) {
    const float* x       = (const float*)d_in[0];
    const float* dw1_w   = (const float*)d_in[1];
    const float* dw1_b   = (const float*)d_in[2];
    const float* bn_dw1  = (const float*)d_in[3];
    const float* f1_w    = (const float*)d_in[4];
    const float* f1_b    = (const float*)d_in[5];
    const float* f2_w    = (const float*)d_in[6];
    const float* f2_b    = (const float*)d_in[7];
    const float* g_w     = (const float*)d_in[8];
    const float* g_b     = (const float*)d_in[9];
    const float* bn_g    = (const float*)d_in[10];
    const float* dw2_w   = (const float*)d_in[11];
    const float* dw2_b   = (const float*)d_in[12];
    const float* hatt1_w = (const float*)d_in[13];
    const float* vatt1_w = (const float*)d_in[14];
    const float* hatt2_w = (const float*)d_in[15];
    const float* vatt2_w = (const float*)d_in[16];
    const float* bn_mra  = (const float*)d_in[17];
    const float* bcdt_w  = (const float*)d_in[18];
    const float* ssd_dw  = (const float*)d_in[19];
    const float* hz_w    = (const float*)d_in[20];
    const float* out_w   = (const float*)d_in[21];
    const float* A_param = (const float*)d_in[22];
    const float* D_param = (const float*)d_in[23];
    const float* qkv_w   = (const float*)d_in[24];
    const float* proj_w  = (const float*)d_in[25];
    const float* bn_n4   = (const float*)d_in[26];
    const float* mlp1_w  = (const float*)d_in[27];
    const float* bn_mlp  = (const float*)d_in[28];
    const float* mlp2_w  = (const float*)d_in[29];
    const float* bn_n1   = (const float*)d_in[30];
    float* out = (float*)d_out;

    float* scr = nullptr;
    cudaGetSymbolAddress((void**)&scr, g_scr);
    float* x1o   = scr + O_X1O;
    float* Wbuf  = scr + O_W;
    float* t2    = scr + O_T2;
    float* tmp1  = scr + O_TMP1;
    float* xt    = scr + O_XT;
    float* att   = scr + O_ATT;
    float* bcdt0 = scr + O_BCDT0;
    float* bcdt  = scr + O_BCDT;
    float* hbuf  = scr + O_H;
    float* h2    = scr + O_H2;
    float* ubuf  = scr + O_U;
    float* qkv   = scr + O_QKV;
    float* obuf  = scr + O_O;
    float* xa    = scr + O_XA;
    float* m1    = scr + O_M1;

    const long XBS = (long)ND * NL;
    const long C64 = (long)NC * NL;
    const long C128 = (long)NHID * NL;
    const long C192 = (long)192 * NL;
    const int PT = (NPAIRS + 127) / 128;  // 25 pixel-pair tiles

    // ---- branch 1 ----
    dw7x7_k<<<NB * NC, 256>>>(x, XBS, dw1_w, dw1_b, bn_dw1, x1o, C64);
    star_k<<<dim3(NHID / 16, PT), 128>>>(x1o, f1_w, f1_b, f2_w, f2_b, t2);
    pwconv_k<128><<<dim3(NC / 16, PT), 128>>>(t2, C128, g_w, NC, g_b, bn_g,
                                              nullptr, 0, tmp1, C64, M_BN);
    dw7x7_k<<<NB * NC, 256>>>(tmp1, C64, dw2_w, dw2_b, nullptr, xa, XBS);

    // ---- branch 2 ----
    pool_blur_k<<<(NB * NC * 100 + 255) / 256, 256>>>(x, xt);
    mra_att_k<<<NB * NC, 192>>>(xt, hatt1_w, vatt1_w, hatt2_w, vatt2_w, bn_mra, att);
    mra_apply_k<<<(NB * NC * NL + 255) / 256, 256>>>(x, att, xa);

    // ---- branch 3 ----
    pwconv_k<64><<<dim3(192 / 16, PT), 128>>>(x + 128 * NL, XBS, bcdt_w, 192, nullptr,
                                              nullptr, nullptr, 0, bcdt0, C192, M_NONE);
    dw3x3_k<<<NB * 192, 256>>>(bcdt0, ssd_dw, bcdt);
    ssd_W_k<<<NB * NS, 256>>>(bcdt, A_param, Wbuf);
    ssd_h_k<<<dim3(8, 8, NB), 256>>>(x, Wbuf, hbuf);
    ssd_mix1_k<<<dim3(4, NB), 256>>>(hbuf, hz_w, D_param, ubuf);
    ssd_mix2_k<<<dim3(4, NB), 256>>>(ubuf, out_w, h2);
    ssd_out_k<<<dim3(4, 4, NB), 196>>>(h2, bcdt, xa);

    // ---- branch 4 ----
    pwconv_k<64><<<dim3(192 / 16, PT), 128>>>(x + 192 * NL, XBS, qkv_w, 192, nullptr,
                                              nullptr, nullptr, 0, qkv, C192, M_NONE);
    attn_k<<<NB * NHEAD * 7, 128>>>(qkv, obuf);
    pwconv_k<64><<<dim3(NC / 16, PT), 128>>>(obuf, C64, proj_w, NC, nullptr, bn_n4,
                                             x + 192 * NL, XBS, xa + 192 * NL, XBS,
                                             M_ADD_BN);

    // ---- merge MLP + residual ----
    pwconv_k<256><<<dim3(NHID / 16, PT), 128>>>(xa, XBS, mlp1_w, NHID, nullptr, bn_mlp,
                                                nullptr, 0, m1, C128, M_BN_RELU);
    pwconv_k<128><<<dim3(ND / 16, PT), 128>>>(m1, C128, mlp2_w, ND, nullptr, bn_n1,
                                              x, XBS, out, XBS, M_BN_ADD);
}

// round 5
// speedup vs baseline: 3.9953x; 1.4318x over previous
#include <cuda_runtime.h>
#include <math.h>

// ---------------- static config ----------------
static constexpr int NB = 8;
static constexpr int ND = 256;
static constexpr int NC = 64;
static constexpr int NHID = 128;
static constexpr int NS = 64;
static constexpr int NHH = 28, NWW = 28;
static constexpr int NL = NHH * NWW;      // 784
static constexpr int NHEAD = 16;
static constexpr int NPAIRS = NB * NL / 2;  // 3136
static constexpr int PPB = NL / 2;          // 392

// ---------------- scratch arena ----------------
static constexpr long O_X1O   = 0;                          // (8,64,784)
static constexpr long O_W     = O_X1O   + (long)NB*NC*NL;   // (8,64,784)
static constexpr long O_T2    = O_W     + (long)NB*NS*NL;   // (8,128,784)
static constexpr long O_TMP1  = O_T2    + (long)NB*NHID*NL; // (8,64,784)
static constexpr long O_BCDT0 = O_TMP1  + (long)NB*NC*NL;   // (8,192,784)
static constexpr long O_BCDT  = O_BCDT0 + (long)NB*192*NL;  // (8,192,784)
static constexpr long O_H     = O_BCDT  + (long)NB*192*NL;  // (8,64,64)
static constexpr long O_H2    = O_H     + (long)NB*NC*NS;   // (8,64,64)
static constexpr long O_U     = O_H2    + (long)NB*NC*NS;   // (8,64,64)
static constexpr long O_QKV   = O_U     + (long)NB*NC*NS;   // (8,192,784)
static constexpr long O_O     = O_QKV   + (long)NB*192*NL;  // (8,64,784)
static constexpr long O_XA    = O_O     + (long)NB*NC*NL;   // (8,256,784)
static constexpr long O_M1    = O_XA    + (long)NB*ND*NL;   // (8,128,784)
static constexpr long SCR_TOTAL = O_M1 + (long)NB*NHID*NL;

__device__ __align__(16) float g_scr[SCR_TOTAL];

enum { M_NONE = 0, M_ADD_BN, M_BN_RELU, M_BN_ADD, M_BN };

// ---------------- pointwise conv, pixel-pair tiled ----------------
template <int CIN>
__global__ void pwconv_k(const float* __restrict__ in, long ibs,
                         const float* __restrict__ w, int cout,
                         const float* __restrict__ bias,
                         const float* __restrict__ bnp,
                         const float* __restrict__ res, long rbs,
                         float* __restrict__ out, long obs, int mode) {
    constexpr int OT = 16;
    __shared__ float ws[CIN * OT];
    int obase = blockIdx.x * OT;
    for (int idx = threadIdx.x; idx < CIN * OT; idx += 128) {
        int c = idx >> 4, i = idx & 15;
        ws[idx] = w[(long)(obase + i) * CIN + c];
    }
    __syncthreads();
    int pp = blockIdx.y * 128 + threadIdx.x;
    if (pp >= NPAIRS) return;
    int b = pp / PPB;
    int l = (pp % PPB) * 2;
    const float2* ip2 = reinterpret_cast<const float2*>(in + (long)b * ibs + l);

    float a0[OT], a1[OT];
#pragma unroll
    for (int i = 0; i < OT; i++) { a0[i] = 0.f; a1[i] = 0.f; }
#pragma unroll 4
    for (int c = 0; c < CIN; c++) {
        float2 xv = ip2[c * (NL / 2)];
        const float* wc = ws + c * OT;
#pragma unroll
        for (int i = 0; i < OT; i++) {
            float wv = wc[i];
            a0[i] += wv * xv.x;
            a1[i] += wv * xv.y;
        }
    }
#pragma unroll
    for (int i = 0; i < OT; i++) {
        int o = obase + i;
        float s0 = a0[i], s1 = a1[i];
        if (bias) { s0 += bias[o]; s1 += bias[o]; }
        if (mode >= M_ADD_BN) {
            long roff = (long)b * rbs + (long)o * NL + l;
            if (mode == M_ADD_BN) {
                float2 rv = *reinterpret_cast<const float2*>(res + roff);
                s0 += rv.x; s1 += rv.y;
            }
            float g = bnp[o], be = bnp[cout + o], mm = bnp[2 * cout + o], vv = bnp[3 * cout + o];
            float sc = g * rsqrtf(vv + 1e-5f);
            s0 = (s0 - mm) * sc + be;
            s1 = (s1 - mm) * sc + be;
            if (mode == M_BN_RELU) { s0 = fmaxf(s0, 0.f); s1 = fmaxf(s1, 0.f); }
            if (mode == M_BN_ADD) {
                float2 rv = *reinterpret_cast<const float2*>(res + roff);
                s0 += rv.x; s1 += rv.y;
            }
        }
        *reinterpret_cast<float2*>(out + (long)b * obs + (long)o * NL + l) =
            make_float2(s0, s1);
    }
}

// ---------------- fused star MLP ----------------
__global__ void star_k(const float* __restrict__ in,
                       const float* __restrict__ w1, const float* __restrict__ b1,
                       const float* __restrict__ w2, const float* __restrict__ b2,
                       float* __restrict__ out) {
    constexpr int OT = 16, CIN = NC;
    __shared__ float ws1[CIN * OT], ws2[CIN * OT];
    int obase = blockIdx.x * OT;
    for (int idx = threadIdx.x; idx < CIN * OT; idx += 128) {
        int c = idx >> 4, i = idx & 15;
        ws1[idx] = w1[(long)(obase + i) * CIN + c];
        ws2[idx] = w2[(long)(obase + i) * CIN + c];
    }
    __syncthreads();
    int pp = blockIdx.y * 128 + threadIdx.x;
    if (pp >= NPAIRS) return;
    int b = pp / PPB;
    int l = (pp % PPB) * 2;
    const float2* ip2 = reinterpret_cast<const float2*>(in + (long)b * NC * NL + l);

    float p0[OT], p1[OT], q0[OT], q1[OT];
#pragma unroll
    for (int i = 0; i < OT; i++) { p0[i] = p1[i] = q0[i] = q1[i] = 0.f; }
#pragma unroll 4
    for (int c = 0; c < CIN; c++) {
        float2 xv = ip2[c * (NL / 2)];
        const float* w1c = ws1 + c * OT;
        const float* w2c = ws2 + c * OT;
#pragma unroll
        for (int i = 0; i < OT; i++) {
            p0[i] += w1c[i] * xv.x; p1[i] += w1c[i] * xv.y;
            q0[i] += w2c[i] * xv.x; q1[i] += w2c[i] * xv.y;
        }
    }
#pragma unroll
    for (int i = 0; i < OT; i++) {
        int o = obase + i;
        float h0 = fminf(fmaxf(p0[i] + b1[o], 0.f), 6.f);
        float h1 = fminf(fmaxf(p1[i] + b1[o], 0.f), 6.f);
        float s0 = h0 * (q0[i] + b2[o]);
        float s1 = h1 * (q1[i] + b2[o]);
        *reinterpret_cast<float2*>(out + ((long)b * NHID + o) * NL + l) =
            make_float2(s0, s1);
    }
}

// ---------------- depthwise 7x7: 2 px/thread, shared row loads ----------------
__global__ void dw7x7_k(const float* __restrict__ in, long ibs,
                        const float* __restrict__ w, const float* __restrict__ bias,
                        const float* __restrict__ bnp,
                        float* __restrict__ out, long obs) {
    int bc = blockIdx.x;
    int c = bc % NC, b = bc / NC;
    const float* ip = in + (long)b * ibs + (long)c * NL;
    __shared__ float pl[34 * 34];
    __shared__ float wsh[49];
    int t = threadIdx.x;  // 392
    for (int i = t; i < 34 * 34; i += 392) pl[i] = 0.f;
    if (t < 49) wsh[t] = w[c * 49 + t];
    __syncthreads();
    {
        int l = t * 2;
        int y = l / NWW, x = l % NWW;
        float2 v = *reinterpret_cast<const float2*>(ip + l);
        pl[(y + 3) * 34 + x + 3] = v.x;
        pl[(y + 3) * 34 + x + 4] = v.y;
    }
    __syncthreads();
    float sc = 1.f, sh = 0.f;
    if (bnp) {
        float g = bnp[c], be = bnp[NC + c], mm = bnp[2 * NC + c], vv = bnp[3 * NC + c];
        sc = g * rsqrtf(vv + 1e-5f);
        sh = be - mm * sc;
    }
    float bi = bias[c];
    int y = t / 14, x0 = (t % 14) * 2;
    float s0 = 0.f, s1 = 0.f;
#pragma unroll
    for (int ky = 0; ky < 7; ky++) {
        float r[8];
        const float* row = pl + (y + ky) * 34 + x0;
#pragma unroll
        for (int kx = 0; kx < 8; kx++) r[kx] = row[kx];
#pragma unroll
        for (int kx = 0; kx < 7; kx++) {
            float wv = wsh[ky * 7 + kx];
            s0 += wv * r[kx];
            s1 += wv * r[kx + 1];
        }
    }
    s0 = (s0 + bi) * sc + sh;
    s1 = (s1 + bi) * sc + sh;
    *reinterpret_cast<float2*>(out + (long)b * obs + (long)c * NL + y * NWW + x0) =
        make_float2(s0, s1);
}

// ---------------- depthwise 3x3 (192 ch) ----------------
__global__ void dw3x3_k(const float* __restrict__ in, const float* __restrict__ w,
                        float* __restrict__ out) {
    int bc = blockIdx.x;
    int c = bc % 192;
    const float* ip = in + (long)bc * NL;
    __shared__ float pl[30 * 30];
    __shared__ float wsh[9];
    int t = threadIdx.x;
    for (int i = t; i < 30 * 30; i += 256) pl[i] = 0.f;
    if (t < 9) wsh[t] = w[c * 9 + t];
    __syncthreads();
    for (int i = t; i < NL; i += 256) {
        int y = i / NWW, x = i % NWW;
        pl[(y + 1) * 30 + x + 1] = ip[i];
    }
    __syncthreads();
    for (int i = t; i < NL; i += 256) {
        int y = i / NWW, x = i % NWW;
        float s = 0.f;
#pragma unroll
        for (int ky = 0; ky < 3; ky++)
#pragma unroll
            for (int kx = 0; kx < 3; kx++)
                s += wsh[ky * 3 + kx] * pl[(y + ky) * 30 + x + kx];
        out[(long)bc * NL + i] = s;
    }
}

// ---------------- branch 2 fully fused: pool+blur+MRA+sigmoid+apply ----------------
__global__ void mra_branch_k(const float* __restrict__ x,
                             const float* __restrict__ h1w, const float* __restrict__ v1w,
                             const float* __restrict__ h2w, const float* __restrict__ v2w,
                             const float* __restrict__ bnp, float* __restrict__ xa) {
    int bc = blockIdx.x;
    int c = bc % NC, b = bc / NC;
    const float* ip = x + ((long)b * ND + NC + c) * NL;
    __shared__ float xp[NL], mp[NL];
    __shared__ float xs[100], ht[190], vt[190], c2[190], c2v[190], att_s[100];
    int t = threadIdx.x;  // 196
    for (int i = t; i < NL; i += 196) xp[i] = ip[i];
    __syncthreads();
    // maxpool 3x3 s1 p1
    for (int i = t; i < NL; i += 196) {
        int y = i / NWW, xx = i % NWW;
        float mx = -1e30f;
        for (int dy = -1; dy <= 1; dy++) {
            int yy = y + dy;
            if (yy < 0 || yy >= NHH) continue;
            for (int dx = -1; dx <= 1; dx++) {
                int xxx = xx + dx;
                if (xxx < 0 || xxx >= NWW) continue;
                mx = fmaxf(mx, xp[yy * NWW + xxx]);
            }
        }
        mp[i] = mx;
    }
    __syncthreads();
    // blurpool f4 s3, reflect pad (1,2)
    if (t < 100) {
        int i = t / 10, j = t % 10;
        const float filt[4] = {1.f, 3.f, 3.f, 1.f};
        float s = 0.f;
        for (int fy = 0; fy < 4; fy++) {
            int oy = 3 * i + fy - 1;
            if (oy < 0) oy = -oy;
            if (oy >= NHH) oy = 2 * NHH - 2 - oy;
            for (int fx = 0; fx < 4; fx++) {
                int ox = 3 * j + fx - 1;
                if (ox < 0) ox = -ox;
                if (ox >= NWW) ox = 2 * NWW - 2 - ox;
                s += filt[fy] * filt[fx] * mp[oy * NWW + ox];
            }
        }
        xs[t] = s * (1.f / 64.f);
    }
    __syncthreads();
    if (t < 190) {
        {
            int row = t / 20, col = t % 20;
            ht[t] = (col < 10) ? xs[row * 10 + col] : 0.f;
        }
        {
            int a = t / 10, b2 = t % 10;
            int k = b2 * 19 + a, row = k / 20, col = k % 20;
            vt[t] = (col < 10) ? xs[col * 10 + row] : 0.f;
        }
    }
    __syncthreads();
    if (t < 190) {
        {
            int r = t / 19, j = t % 19;
            float s = 0.f;
            for (int ky = 0; ky < 11; ky++) {
                int yy = r + ky - 5;
                if (yy < 0 || yy >= 10) continue;
                for (int kx = 0; kx < 3; kx++) {
                    int xx = j + kx - 1;
                    if (xx < 0 || xx >= 19) continue;
                    s += h2w[c * 33 + ky * 3 + kx] * ht[yy * 19 + xx];
                }
            }
            c2[t] = s;
        }
        {
            int y = t / 10, x2 = t % 10;
            float s = 0.f;
            for (int ky = 0; ky < 3; ky++) {
                int yy = y + ky - 1;
                if (yy < 0 || yy >= 19) continue;
                for (int kx = 0; kx < 11; kx++) {
                    int xx = x2 + kx - 5;
                    if (xx < 0 || xx >= 10) continue;
                    s += v2w[c * 33 + ky * 11 + kx] * vt[yy * 10 + xx];
                }
            }
            c2v[t] = s;
        }
    }
    __syncthreads();
    if (t < 100) {
        int y = t / 10, xx = t % 10;
        float s = 0.f;
        for (int ky = 0; ky < 11; ky++) {
            int yy = y + ky - 5;
            if (yy < 0 || yy >= 10) continue;
            for (int kx = 0; kx < 3; kx++) {
                int xxx = xx + kx - 1;
                if (xxx < 0 || xxx >= 10) continue;
                s += h1w[c * 33 + ky * 3 + kx] * xs[yy * 10 + xxx];
            }
        }
        for (int ky = 0; ky < 3; ky++) {
            int yy = y + ky - 1;
            if (yy < 0 || yy >= 10) continue;
            for (int kx = 0; kx < 11; kx++) {
                int xxx = xx + kx - 5;
                if (xxx < 0 || xxx >= 10) continue;
                s += v1w[c * 33 + ky * 11 + kx] * xs[yy * 10 + xxx];
            }
        }
        s += c2[y * 20 + xx];
        int k4 = xx * 20 + y;
        s += c2v[(k4 % 19) * 10 + (k4 / 19)];
        float g = bnp[c], be = bnp[NC + c], mm = bnp[2 * NC + c], vv = bnp[3 * NC + c];
        float sc = g * rsqrtf(vv + 1e-5f);
        s = (s - mm) * sc + be;
        att_s[t] = 1.f / (1.f + __expf(-s));
    }
    __syncthreads();
    // apply gate (nearest upsample 10 -> 28)
    float* op = xa + (long)b * ND * NL + (long)(NC + c) * NL;
    for (int i = t; i < NL; i += 196) {
        int y = i / NWW, xx = i % NWW;
        int yo = (y * 10) / NHH, xo = (xx * 10) / NWW;
        op[i] = xp[i] * att_s[yo * 10 + xo];
    }
}

// ---------------- SSD softmax weights ----------------
__global__ void ssd_W_k(const float* __restrict__ bcdt, const float* __restrict__ A_param,
                        float* __restrict__ W) {
    int b = blockIdx.x / NS, s = blockIdx.x % NS;
    const float* dt = bcdt + ((long)b * 192 + 128 + s) * NL;
    const float* Bm = bcdt + ((long)b * 192 + s) * NL;
    float* Wp = W + ((long)b * NS + s) * NL;
    __shared__ float red[256];
    int t = threadIdx.x;
    float ap = A_param[s];
    float mx = -1e30f;
    for (int l = t; l < NL; l += 256) mx = fmaxf(mx, dt[l] + ap);
    red[t] = mx;
    __syncthreads();
    for (int o = 128; o > 0; o >>= 1) {
        if (t < o) red[t] = fmaxf(red[t], red[t + o]);
        __syncthreads();
    }
    mx = red[0];
    __syncthreads();
    float sum = 0.f;
    for (int l = t; l < NL; l += 256) {
        float e = __expf(dt[l] + ap - mx);
        Wp[l] = e;
        sum += e;
    }
    red[t] = sum;
    __syncthreads();
    for (int o = 128; o > 0; o >>= 1) {
        if (t < o) red[t] += red[t + o];
        __syncthreads();
    }
    float inv = 1.f / red[0];
    __syncthreads();
    for (int l = t; l < NL; l += 256) Wp[l] = Wp[l] * inv * Bm[l];
}

// ---------------- SSD h = xs @ W^T ----------------
__global__ void ssd_h_k(const float* __restrict__ x, const float* __restrict__ W,
                        float* __restrict__ h) {
    int b = blockIdx.z;
    int sbase = blockIdx.y * 8;
    __shared__ float Wt[8][NL];
    int t = threadIdx.x;
    for (int i = t; i < 8 * NL; i += 256) {
        int si = i / NL, l = i % NL;
        Wt[si][l] = W[((long)b * NS + sbase + si) * NL + l];
    }
    __syncthreads();
    int warp = t / 32, lane = t % 32;
    int c = blockIdx.x * 8 + warp;
    const float* xs = x + ((long)b * ND + 128 + c) * NL;
    float acc[8];
#pragma unroll
    for (int i = 0; i < 8; i++) acc[i] = 0.f;
    for (int l = lane; l < NL; l += 32) {
        float xv = xs[l];
#pragma unroll
        for (int i = 0; i < 8; i++) acc[i] += xv * Wt[i][l];
    }
#pragma unroll
    for (int i = 0; i < 8; i++) {
        for (int o = 16; o > 0; o >>= 1) acc[i] += __shfl_down_sync(0xffffffff, acc[i], o);
    }
    if (lane == 0) {
#pragma unroll
        for (int i = 0; i < 8; i++)
            h[((long)b * NC + c) * NS + sbase + i] = acc[i];
    }
}

// ---------------- SSD mix 1 ----------------
__global__ void ssd_mix1_k(const float* __restrict__ h, const float* __restrict__ hzw,
                           const float* __restrict__ D, float* __restrict__ u) {
    int b = blockIdx.y, og = blockIdx.x, t = threadIdx.x;
    __shared__ float hs[NC * NS];
    __shared__ float w1[16 * NC], w2[16 * NC];
    for (int i = t; i < NC * NS; i += 256) hs[i] = h[(long)b * NC * NS + i];
    for (int i = t; i < 16 * NC; i += 256) {
        int o = i / NC, c = i % NC;
        w1[i] = hzw[(og * 16 + o) * NC + c];
        w2[i] = hzw[(NC + og * 16 + o) * NC + c];
    }
    __syncthreads();
    float Dv = D[0];
    for (int idx = t; idx < 16 * NS; idx += 256) {
        int o = idx / NS, s = idx % NS;
        float s1 = 0.f, s2 = 0.f;
#pragma unroll 4
        for (int c = 0; c < NC; c++) {
            float hv = hs[c * NS + s];
            s1 += w1[o * NC + c] * hv;
            s2 += w2[o * NC + c] * hv;
        }
        float sil = s2 / (1.f + __expf(-s2));
        u[((long)b * NC + og * 16 + o) * NS + s] = s1 * sil + s1 * Dv;
    }
}

// ---------------- SSD mix 2 ----------------
__global__ void ssd_mix2_k(const float* __restrict__ u, const float* __restrict__ ow,
                           float* __restrict__ h2) {
    int b = blockIdx.y, og = blockIdx.x, t = threadIdx.x;
    __shared__ float us[NC * NS];
    __shared__ float wsm[16 * NC];
    for (int i = t; i < NC * NS; i += 256) us[i] = u[(long)b * NC * NS + i];
    for (int i = t; i < 16 * NC; i += 256)
        wsm[i] = ow[(og * 16 + i / NC) * NC + i % NC];
    __syncthreads();
    for (int idx = t; idx < 16 * NS; idx += 256) {
        int o = idx / NS, s = idx % NS;
        float acc = 0.f;
#pragma unroll 4
        for (int c = 0; c < NC; c++) acc += wsm[o * NC + c] * us[c * NS + s];
        h2[((long)b * NC + og * 16 + o) * NS + s] = acc;
    }
}

// ---------------- SSD out ----------------
__global__ void ssd_out_k(const float* __restrict__ h2, const float* __restrict__ bcdt,
                          float* __restrict__ xa) {
    int b = blockIdx.z, lt = blockIdx.y, cg = blockIdx.x;
    __shared__ float hst[NS * 16];
    int t = threadIdx.x;  // 196
    for (int i = t; i < 16 * NS; i += 196) {
        int s = i / 16, ii = i % 16;
        hst[i] = h2[((long)b * NC + cg * 16 + ii) * NS + s];
    }
    __syncthreads();
    int l = lt * 196 + t;
    const float* Cm = bcdt + ((long)b * 192 + 64) * NL + l;
    float acc[16];
#pragma unroll
    for (int i = 0; i < 16; i++) acc[i] = 0.f;
#pragma unroll 4
    for (int s = 0; s < NS; s++) {
        float cv = Cm[(long)s * NL];
        const float* hp = hst + s * 16;
#pragma unroll
        for (int i = 0; i < 16; i++) acc[i] += hp[i] * cv;
    }
#pragma unroll
    for (int i = 0; i < 16; i++)
        xa[(long)b * ND * NL + (long)(128 + cg * 16 + i) * NL + l] = acc[i];
}

// ---------------- GA attention ----------------
__global__ void attn_k(const float* __restrict__ qkv, float* __restrict__ o) {
    int blk = blockIdx.x;
    int rc = blk % 7;
    int bh = blk / 7;
    int head = bh % NHEAD, b = bh / NHEAD;
    __shared__ float Ks[NL * 4], Vs[NL * 4];
    const float* kbase = qkv + ((long)b * 192 + 64 + head * 4) * NL;
    const float* vbase = qkv + ((long)b * 192 + 128 + head * 4) * NL;
    for (int i = threadIdx.x; i < NL * 4; i += blockDim.x) {
        int d = i / NL, l = i % NL;
        Ks[l * 4 + d] = kbase[i];
        Vs[l * 4 + d] = vbase[i];
    }
    __syncthreads();
    int row = rc * 128 + threadIdx.x;
    if (row >= NL) return;
    const float* qb = qkv + ((long)b * 192 + head * 4) * NL;
    float q0 = qb[row] * 0.5f, q1 = qb[NL + row] * 0.5f;
    float q2 = qb[2 * NL + row] * 0.5f, q3 = qb[3 * NL + row] * 0.5f;
    float se = 0.f, a0 = 0.f, a1 = 0.f, a2 = 0.f, a3 = 0.f;
    const float4* K4 = reinterpret_cast<const float4*>(Ks);
    const float4* V4 = reinterpret_cast<const float4*>(Vs);
    for (int l = 0; l < NL; l++) {
        float4 kv = K4[l];
        float s = q0 * kv.x + q1 * kv.y + q2 * kv.z + q3 * kv.w;
        float p = __expf(s);
        float4 vv = V4[l];
        se += p;
        a0 += p * vv.x; a1 += p * vv.y; a2 += p * vv.z; a3 += p * vv.w;
    }
    float inv = 1.f / se;
    float* ob = o + ((long)b * NC + head * 4) * NL;
    ob[row] = a0 * inv;
    ob[NL + row] = a1 * inv;
    ob[2 * NL + row] = a2 * inv;
    ob[3 * NL + row] = a3 * inv;
}

// ---------------- launch (fork-join across 4 streams) ----------------
extern "C" void kernel_launch(void* const* d_in, const int* in_sizes, int n_in,
                              void* d_out, int out_size) {
    const float* x       = (const float*)d_in[0];
    const float* dw1_w   = (const float*)d_in[1];
    const float* dw1_b   = (const float*)d_in[2];
    const float* bn_dw1  = (const float*)d_in[3];
    const float* f1_w    = (const float*)d_in[4];
    const float* f1_b    = (const float*)d_in[5];
    const float* f2_w    = (const float*)d_in[6];
    const float* f2_b    = (const float*)d_in[7];
    const float* g_w     = (const float*)d_in[8];
    const float* g_b     = (const float*)d_in[9];
    const float* bn_g    = (const float*)d_in[10];
    const float* dw2_w   = (const float*)d_in[11];
    const float* dw2_b   = (const float*)d_in[12];
    const float* hatt1_w = (const float*)d_in[13];
    const float* vatt1_w = (const float*)d_in[14];
    const float* hatt2_w = (const float*)d_in[15];
    const float* vatt2_w = (const float*)d_in[16];
    const float* bn_mra  = (const float*)d_in[17];
    const float* bcdt_w  = (const float*)d_in[18];
    const float* ssd_dw  = (const float*)d_in[19];
    const float* hz_w    = (const float*)d_in[20];
    const float* out_w   = (const float*)d_in[21];
    const float* A_param = (const float*)d_in[22];
    const float* D_param = (const float*)d_in[23];
    const float* qkv_w   = (const float*)d_in[24];
    const float* proj_w  = (const float*)d_in[25];
    const float* bn_n4   = (const float*)d_in[26];
    const float* mlp1_w  = (const float*)d_in[27];
    const float* bn_mlp  = (const float*)d_in[28];
    const float* mlp2_w  = (const float*)d_in[29];
    const float* bn_n1   = (const float*)d_in[30];
    float* out = (float*)d_out;

    float* scr = nullptr;
    cudaGetSymbolAddress((void**)&scr, g_scr);
    float* x1o   = scr + O_X1O;
    float* Wbuf  = scr + O_W;
    float* t2    = scr + O_T2;
    float* tmp1  = scr + O_TMP1;
    float* bcdt0 = scr + O_BCDT0;
    float* bcdt  = scr + O_BCDT;
    float* hbuf  = scr + O_H;
    float* h2    = scr + O_H2;
    float* ubuf  = scr + O_U;
    float* qkv   = scr + O_QKV;
    float* obuf  = scr + O_O;
    float* xa    = scr + O_XA;
    float* m1    = scr + O_M1;

    const long XBS = (long)ND * NL;
    const long C64 = (long)NC * NL;
    const long C128 = (long)NHID * NL;
    const long C192 = (long)192 * NL;
    const int PT = (NPAIRS + 127) / 128;

    // streams/events created once, on the (non-captured) correctness call
    static cudaStream_t s1 = nullptr, s2 = nullptr, s3 = nullptr;
    static cudaEvent_t eFork, eJ1, eJ2, eJ3;
    if (!s1) {
        cudaStreamCreateWithFlags(&s1, cudaStreamNonBlocking);
        cudaStreamCreateWithFlags(&s2, cudaStreamNonBlocking);
        cudaStreamCreateWithFlags(&s3, cudaStreamNonBlocking);
        cudaEventCreateWithFlags(&eFork, cudaEventDisableTiming);
        cudaEventCreateWithFlags(&eJ1, cudaEventDisableTiming);
        cudaEventCreateWithFlags(&eJ2, cudaEventDisableTiming);
        cudaEventCreateWithFlags(&eJ3, cudaEventDisableTiming);
    }

    cudaEventRecord(eFork, 0);
    cudaStreamWaitEvent(s1, eFork, 0);
    cudaStreamWaitEvent(s2, eFork, 0);
    cudaStreamWaitEvent(s3, eFork, 0);

    // ---- branch 2 (stream s1): fully fused ----
    mra_branch_k<<<NB * NC, 196, 0, s1>>>(x, hatt1_w, vatt1_w, hatt2_w, vatt2_w,
                                          bn_mra, xa);
    cudaEventRecord(eJ1, s1);

    // ---- branch 3 (stream s2) ----
    pwconv_k<64><<<dim3(192 / 16, PT), 128, 0, s2>>>(x + 128 * NL, XBS, bcdt_w, 192,
                                                     nullptr, nullptr, nullptr, 0,
                                                     bcdt0, C192, M_NONE);
    dw3x3_k<<<NB * 192, 256, 0, s2>>>(bcdt0, ssd_dw, bcdt);
    ssd_W_k<<<NB * NS, 256, 0, s2>>>(bcdt, A_param, Wbuf);
    ssd_h_k<<<dim3(8, 8, NB), 256, 0, s2>>>(x, Wbuf, hbuf);
    ssd_mix1_k<<<dim3(4, NB), 256, 0, s2>>>(hbuf, hz_w, D_param, ubuf);
    ssd_mix2_k<<<dim3(4, NB), 256, 0, s2>>>(ubuf, out_w, h2);
    ssd_out_k<<<dim3(4, 4, NB), 196, 0, s2>>>(h2, bcdt, xa);
    cudaEventRecord(eJ2, s2);

    // ---- branch 4 (stream s3) ----
    pwconv_k<64><<<dim3(192 / 16, PT), 128, 0, s3>>>(x + 192 * NL, XBS, qkv_w, 192,
                                                     nullptr, nullptr, nullptr, 0,
                                                     qkv, C192, M_NONE);
    attn_k<<<NB * NHEAD * 7, 128, 0, s3>>>(qkv, obuf);
    pwconv_k<64><<<dim3(NC / 16, PT), 128, 0, s3>>>(obuf, C64, proj_w, NC, nullptr,
                                                    bn_n4, x + 192 * NL, XBS,
                                                    xa + 192 * NL, XBS, M_ADD_BN);
    cudaEventRecord(eJ3, s3);

    // ---- branch 1 (default stream) ----
    dw7x7_k<<<NB * NC, 392>>>(x, XBS, dw1_w, dw1_b, bn_dw1, x1o, C64);
    star_k<<<dim3(NHID / 16, PT), 128>>>(x1o, f1_w, f1_b, f2_w, f2_b, t2);
    pwconv_k<128><<<dim3(NC / 16, PT), 128>>>(t2, C128, g_w, NC, g_b, bn_g,
                                              nullptr, 0, tmp1, C64, M_BN);
    dw7x7_k<<<NB * NC, 392>>>(tmp1, C64, dw2_w, dw2_b, nullptr, xa, XBS);

    // ---- join ----
    cudaStreamWaitEvent(0, eJ1, 0);
    cudaStreamWaitEvent(0, eJ2, 0);
    cudaStreamWaitEvent(0, eJ3, 0);

    // ---- merge MLP + residual ----
    pwconv_k<256><<<dim3(NHID / 16, PT), 128>>>(xa, XBS, mlp1_w, NHID, nullptr, bn_mlp,
                                                nullptr, 0, m1, C128, M_BN_RELU);
    pwconv_k<128><<<dim3(ND / 16, PT), 128>>>(m1, C128, mlp2_w, ND, nullptr, bn_n1,
                                              x, XBS, out, XBS, M_BN_ADD);
}